// round 7
// baseline (speedup 1.0000x reference)
#include <cuda_runtime.h>
#include <cstdint>

// Problem constants
#define BB 8
#define TT 2048
#define DD 1024
#define QD 128
#define NEGV -1000000000.0f

// Scratch for q, k, v projections (8*2048*128 fp32 each = 8 MB each)
__device__ float g_q[BB * TT * QD];
__device__ float g_k[BB * TT * QD];
__device__ float g_v[BB * TT * QD];
// Canonical fp32 mask (1.0 = keep, 0.0 = masked) + detected dtype kind
__device__ float g_mask[BB * TT];
__device__ int   g_mask_kind;   // 0 = int32, 1 = uint8, 2 = float32

// ---------------------------------------------------------------------------
// Mask dtype sniffer: the harness ships jnp.bool_ as one of uint8/int32/f32.
//   int32 one  = 01 00 00 00   -> bytes @+1 always 0, @+3 always 0
//   f32   one  = 00 00 80 3F   -> bytes @+1 always 0, @+3 = 0x3F when set
//   uint8 data = random 0/1 at every byte -> byte @+1 nonzero somewhere
// So: any nonzero byte at offset%4==1 => uint8; else any nonzero at
// offset%4==3 => float32; else int32. Single CTA, reads exactly 16384 bytes
// (the smallest possible size for any of the three interpretations).
// ---------------------------------------------------------------------------
__global__ void mask_sniff(const uint8_t* __restrict__ m)
{
    __shared__ unsigned r1[256], r3[256];
    unsigned o1 = 0, o3 = 0;
    const uint32_t* w = (const uint32_t*)m;
    for (int i = threadIdx.x; i < (BB * TT) / 4; i += 256) {
        uint32_t v = w[i];
        o1 |= (v >> 8)  & 0xFFu;   // byte offset 1
        o3 |= (v >> 24) & 0xFFu;   // byte offset 3
    }
    r1[threadIdx.x] = o1; r3[threadIdx.x] = o3;
    __syncthreads();
    for (int s = 128; s; s >>= 1) {
        if (threadIdx.x < s) {
            r1[threadIdx.x] |= r1[threadIdx.x + s];
            r3[threadIdx.x] |= r3[threadIdx.x + s];
        }
        __syncthreads();
    }
    if (threadIdx.x == 0)
        g_mask_kind = r1[0] ? 1 : (r3[0] ? 2 : 0);
}

__global__ void mask_expand(const void* __restrict__ m)
{
    int s = blockIdx.x * 256 + threadIdx.x;
    if (s >= BB * TT) return;
    int kind = g_mask_kind;
    float v;
    if (kind == 1)      v = ((const uint8_t*)m)[s] ? 1.0f : 0.0f;
    else if (kind == 2) v = (((const float*)m)[s] != 0.0f) ? 1.0f : 0.0f;
    else                v = ((const int*)m)[s] ? 1.0f : 0.0f;
    g_mask[s] = v;
}

// ---------------------------------------------------------------------------
// Kernel 1: fused projection GEMM.
//   out[M=B*T, 128] = x[M, 1024] @ W^T   for W in {Wq, Wk, Wv}
// Tile: 64(M) x 64(N), BK=16, 256 threads, 4x4 per-thread microtile.
// ---------------------------------------------------------------------------
__global__ __launch_bounds__(256) void proj_kernel(
    const float* __restrict__ x,
    const float* __restrict__ Wq,
    const float* __restrict__ Wk,
    const float* __restrict__ Wv)
{
    __shared__ float As[16][64];   // As[k][m]
    __shared__ float Bs[16][64];   // Bs[k][n]

    const int m0 = blockIdx.x * 64;
    const int n0 = blockIdx.y * 64;
    const int z  = blockIdx.z;
    const float* __restrict__ W = (z == 0) ? Wq : ((z == 1) ? Wk : Wv);
    float* __restrict__ outp    = (z == 0) ? g_q : ((z == 1) ? g_k : g_v);

    const int tid  = threadIdx.x;
    const int ty   = tid >> 4;         // 0..15
    const int tx   = tid & 15;         // 0..15
    const int lrow = tid >> 2;         // 0..63
    const int lk   = (tid & 3) << 2;   // 0,4,8,12

    const float* xg = x + (size_t)(m0 + lrow) * DD + lk;
    const float* wg = W + (size_t)(n0 + lrow) * DD + lk;

    float acc[4][4] = {};

    for (int k0 = 0; k0 < DD; k0 += 16) {
        float4 a = *(const float4*)(xg + k0);
        float4 b = *(const float4*)(wg + k0);
        As[lk + 0][lrow] = a.x; As[lk + 1][lrow] = a.y;
        As[lk + 2][lrow] = a.z; As[lk + 3][lrow] = a.w;
        Bs[lk + 0][lrow] = b.x; Bs[lk + 1][lrow] = b.y;
        Bs[lk + 2][lrow] = b.z; Bs[lk + 3][lrow] = b.w;
        __syncthreads();
        #pragma unroll
        for (int kk = 0; kk < 16; kk++) {
            float4 av = *(const float4*)&As[kk][ty << 2];
            float4 bv = *(const float4*)&Bs[kk][tx << 2];
            float aa[4] = {av.x, av.y, av.z, av.w};
            float bb[4] = {bv.x, bv.y, bv.z, bv.w};
            #pragma unroll
            for (int i = 0; i < 4; i++)
                #pragma unroll
                for (int j = 0; j < 4; j++)
                    acc[i][j] = fmaf(aa[i], bb[j], acc[i][j]);
        }
        __syncthreads();
    }

    #pragma unroll
    for (int i = 0; i < 4; i++) {
        float4 v = make_float4(acc[i][0], acc[i][1], acc[i][2], acc[i][3]);
        *(float4*)&outp[(size_t)(m0 + (ty << 2) + i) * QD + n0 + (tx << 2)] = v;
    }
}

// ---------------------------------------------------------------------------
// Kernel 2: flash attention with key-position mask.
// One CTA handles 64 query rows of one batch; loops over all 2048 keys in
// 64-row tiles with online softmax. 256 threads.
// ---------------------------------------------------------------------------
#define ATTN_SMEM_FLOATS (128*64 + 128*64 + 64*128 + 64*64 + 5*64)
#define ATTN_SMEM_BYTES  (ATTN_SMEM_FLOATS * 4)

__global__ __launch_bounds__(256) void attn_kernel(float* __restrict__ out)
{
    extern __shared__ float sm[];
    float* Qs       = sm;                 // [128][64]  Qs[d][q]
    float* Ks       = Qs + 128 * 64;      // [128][64]  Ks[d][s]
    float* Vs       = Ks + 128 * 64;      // [64][128]  Vs[s][d]
    float* Ps       = Vs + 64 * 128;      // [64][64]   Ps[s][q]
    float* sm_m     = Ps + 64 * 64;       // running max  [64]
    float* sm_sum   = sm_m + 64;          // running sum  [64]
    float* sm_scale = sm_sum + 64;        // rescale      [64]
    float* sm_rmax  = sm_scale + 64;      // tile rowmax  [64]
    float* mk       = sm_rmax + 64;       // mask tile    [64]

    const int tid = threadIdx.x;
    const int b   = blockIdx.y;
    const int t0  = blockIdx.x * 64;
    const int ty  = tid >> 4;   // 0..15
    const int tx  = tid & 15;   // 0..15

    // Load Q tile (64 x 128), transposed into Qs[d][q]
    {
        const float* qg = g_q + (size_t)(b * TT + t0) * QD;
        #pragma unroll
        for (int r = 0; r < 8; r++) {
            int idx = tid + r * 256;          // float4 index, 0..2047
            int row = idx >> 5;               // 0..63
            int dq  = (idx & 31) << 2;        // 0..124
            float4 v = *(const float4*)(qg + row * QD + dq);
            Qs[(dq + 0) * 64 + row] = v.x; Qs[(dq + 1) * 64 + row] = v.y;
            Qs[(dq + 2) * 64 + row] = v.z; Qs[(dq + 3) * 64 + row] = v.w;
        }
    }
    if (tid < 64) { sm_m[tid] = -3.0e38f; sm_sum[tid] = 0.0f; }

    float acc[4][8] = {};

    const float* mg = g_mask + b * TT;
    const float* kg = g_k + (size_t)(b * TT) * QD;
    const float* vg = g_v + (size_t)(b * TT) * QD;

    for (int s0 = 0; s0 < TT; s0 += 64) {
        __syncthreads();  // protect smem from previous iteration / Q load
        if (tid < 64) mk[tid] = mg[s0 + tid];
        #pragma unroll
        for (int r = 0; r < 8; r++) {
            int idx = tid + r * 256;
            int row = idx >> 5;
            int dq  = (idx & 31) << 2;
            float4 kv = *(const float4*)(kg + (s0 + row) * QD + dq);
            Ks[(dq + 0) * 64 + row] = kv.x; Ks[(dq + 1) * 64 + row] = kv.y;
            Ks[(dq + 2) * 64 + row] = kv.z; Ks[(dq + 3) * 64 + row] = kv.w;
            float4 vv = *(const float4*)(vg + (s0 + row) * QD + dq);
            *(float4*)&Vs[row * 128 + dq] = vv;
        }
        __syncthreads();

        // GEMM1: logits[4q][4s] = Q . K^T over d=128
        float l[4][4] = {};
        #pragma unroll 8
        for (int d = 0; d < 128; d++) {
            float4 a  = *(const float4*)&Qs[d * 64 + (ty << 2)];
            float4 bq = *(const float4*)&Ks[d * 64 + (tx << 2)];
            float aa[4] = {a.x, a.y, a.z, a.w};
            float bb[4] = {bq.x, bq.y, bq.z, bq.w};
            #pragma unroll
            for (int i = 0; i < 4; i++)
                #pragma unroll
                for (int j = 0; j < 4; j++)
                    l[i][j] = fmaf(aa[i], bb[j], l[i][j]);
        }

        // Mask + per-tile row max
        float mkj[4];
        #pragma unroll
        for (int j = 0; j < 4; j++) mkj[j] = mk[(tx << 2) + j];
        float rm[4];
        #pragma unroll
        for (int i = 0; i < 4; i++) {
            #pragma unroll
            for (int j = 0; j < 4; j++)
                l[i][j] = (mkj[j] != 0.0f) ? l[i][j] : NEGV;
            rm[i] = fmaxf(fmaxf(l[i][0], l[i][1]), fmaxf(l[i][2], l[i][3]));
        }
        #pragma unroll
        for (int i = 0; i < 4; i++) {
            #pragma unroll
            for (int off = 8; off; off >>= 1)
                rm[i] = fmaxf(rm[i], __shfl_xor_sync(0xffffffffu, rm[i], off));
        }
        if (tx == 0) {
            #pragma unroll
            for (int i = 0; i < 4; i++) sm_rmax[(ty << 2) + i] = rm[i];
        }
        __syncthreads();

        // Online softmax state update (one thread per row)
        if (tid < 64) {
            float mo = sm_m[tid];
            float mn = fmaxf(mo, sm_rmax[tid]);
            float sc = __expf(mo - mn);
            sm_scale[tid] = sc;
            sm_m[tid]     = mn;
            sm_sum[tid]  *= sc;
        }
        __syncthreads();

        // p = exp(l - m_new), write Ps[s][q], accumulate row sums
        float rs[4];
        #pragma unroll
        for (int i = 0; i < 4; i++) {
            int row = (ty << 2) + i;
            float mn = sm_m[row];
            float p[4];
            #pragma unroll
            for (int j = 0; j < 4; j++) {
                p[j] = (mkj[j] != 0.0f) ? __expf(l[i][j] - mn) : 0.0f;
                Ps[((tx << 2) + j) * 64 + row] = p[j];
            }
            rs[i] = (p[0] + p[1]) + (p[2] + p[3]);
        }
        #pragma unroll
        for (int i = 0; i < 4; i++) {
            #pragma unroll
            for (int off = 8; off; off >>= 1)
                rs[i] += __shfl_xor_sync(0xffffffffu, rs[i], off);
        }
        if (tx == 0) {
            #pragma unroll
            for (int i = 0; i < 4; i++) sm_sum[(ty << 2) + i] += rs[i];
        }
        // Rescale accumulator (same ty->row mapping as GEMM2)
        #pragma unroll
        for (int i = 0; i < 4; i++) {
            float sc = sm_scale[(ty << 2) + i];
            #pragma unroll
            for (int j = 0; j < 8; j++) acc[i][j] *= sc;
        }
        __syncthreads();  // Ps fully written

        // GEMM2: acc[4q][8d] += P[64q][64s] @ V[64s][128d]
        #pragma unroll 4
        for (int ss = 0; ss < 64; ss++) {
            float4 a  = *(const float4*)&Ps[ss * 64 + (ty << 2)];
            float4 b0 = *(const float4*)&Vs[ss * 128 + (tx << 3)];
            float4 b1 = *(const float4*)&Vs[ss * 128 + (tx << 3) + 4];
            float aa[4] = {a.x, a.y, a.z, a.w};
            float bb[8] = {b0.x, b0.y, b0.z, b0.w, b1.x, b1.y, b1.z, b1.w};
            #pragma unroll
            for (int i = 0; i < 4; i++)
                #pragma unroll
                for (int j = 0; j < 8; j++)
                    acc[i][j] = fmaf(aa[i], bb[j], acc[i][j]);
        }
    }
    __syncthreads();

    // Final normalize + store
    #pragma unroll
    for (int i = 0; i < 4; i++) {
        int row = (ty << 2) + i;
        float inv = 1.0f / sm_sum[row];
        float4 o0 = make_float4(acc[i][0] * inv, acc[i][1] * inv,
                                acc[i][2] * inv, acc[i][3] * inv);
        float4 o1 = make_float4(acc[i][4] * inv, acc[i][5] * inv,
                                acc[i][6] * inv, acc[i][7] * inv);
        float* op = out + (size_t)(b * TT + t0 + row) * QD + (tx << 3);
        *(float4*)(op + 0) = o0;
        *(float4*)(op + 4) = o1;
    }
}

// ---------------------------------------------------------------------------
// Launch
// ---------------------------------------------------------------------------
extern "C" void kernel_launch(void* const* d_in, const int* in_sizes, int n_in,
                              void* d_out, int out_size)
{
    const float* x    = (const float*)d_in[0];
    const void*  mask = d_in[1];                 // dtype detected on device
    const float* Wq   = (const float*)d_in[2];
    const float* Wk   = (const float*)d_in[3];
    const float* Wv   = (const float*)d_in[4];
    float*       out  = (float*)d_out;
    (void)in_sizes; (void)n_in; (void)out_size;

    // Mask canonicalization (dtype sniff + expand to fp32)
    mask_sniff<<<1, 256>>>((const uint8_t*)mask);
    mask_expand<<<(BB * TT + 255) / 256, 256>>>(mask);

    // QKV projections: M tiles = 16384/64 = 256, N tiles = 128/64 = 2, 3 weights
    dim3 g1(256, 2, 3);
    proj_kernel<<<g1, 256>>>(x, Wq, Wk, Wv);

    // Flash attention: 32 query tiles x 8 batches
    cudaFuncSetAttribute(attn_kernel,
                         cudaFuncAttributeMaxDynamicSharedMemorySize,
                         ATTN_SMEM_BYTES);
    dim3 g2(TT / 64, BB);
    attn_kernel<<<g2, 256, ATTN_SMEM_BYTES>>>(out);
}

// round 9
// speedup vs baseline: 3.3569x; 3.3569x over previous
#include <cuda_runtime.h>
#include <cuda_bf16.h>
#include <cstdint>

#define BB 8
#define TT 2048
#define DD 1024
#define QD 128

// ---------------- global scratch ----------------
__device__ __nv_bfloat16 g_x_hi[(size_t)BB*TT*DD];   // 33.5 MB
__device__ __nv_bfloat16 g_x_lo[(size_t)BB*TT*DD];
__device__ __nv_bfloat16 g_w_hi[3*QD*DD];
__device__ __nv_bfloat16 g_w_lo[3*QD*DD];
__device__ __nv_bfloat16 g_q_hi[BB*TT*QD];
__device__ __nv_bfloat16 g_q_lo[BB*TT*QD];
__device__ __nv_bfloat16 g_k_hi[BB*TT*QD];
__device__ __nv_bfloat16 g_k_lo[BB*TT*QD];
__device__ __nv_bfloat16 g_v_hi[BB*TT*QD];           // row-major [b][t][d]
__device__ __nv_bfloat16 g_v_lo[BB*TT*QD];
__device__ float g_mask[BB*TT];
__device__ int   g_mask_kind;

// ---------------- helpers ----------------
__device__ __forceinline__ uint32_t smem_u32(const void* p) {
    uint32_t a;
    asm("{ .reg .u64 t; cvta.to.shared.u64 t, %1; cvt.u32.u64 %0, t; }" : "=r"(a) : "l"(p));
    return a;
}
__device__ __forceinline__ uint32_t pk(__nv_bfloat16 a, __nv_bfloat16 b) {
    return (uint32_t)__bfloat16_as_ushort(a) | ((uint32_t)__bfloat16_as_ushort(b) << 16);
}
// split two floats into packed bf16 hi and lo words
__device__ __forceinline__ void split2(float a, float b, uint32_t& h, uint32_t& l) {
    __nv_bfloat16 ha = __float2bfloat16_rn(a);
    __nv_bfloat16 hb = __float2bfloat16_rn(b);
    __nv_bfloat16 la = __float2bfloat16_rn(a - __bfloat162float(ha));
    __nv_bfloat16 lb = __float2bfloat16_rn(b - __bfloat162float(hb));
    h = pk(ha, hb); l = pk(la, lb);
}
__device__ __forceinline__ void ldm4(uint32_t r[4], uint32_t a) {
    asm volatile("ldmatrix.sync.aligned.m8n8.x4.shared.b16 {%0,%1,%2,%3}, [%4];"
        : "=r"(r[0]), "=r"(r[1]), "=r"(r[2]), "=r"(r[3]) : "r"(a));
}
__device__ __forceinline__ void ldm4t(uint32_t r[4], uint32_t a) {
    asm volatile("ldmatrix.sync.aligned.m8n8.x4.trans.shared.b16 {%0,%1,%2,%3}, [%4];"
        : "=r"(r[0]), "=r"(r[1]), "=r"(r[2]), "=r"(r[3]) : "r"(a));
}
// D += A(16x16 bf16) x B(16x8 bf16), fp32 accum
__device__ __forceinline__ void mma_bf16(float* c, const uint32_t* a, const uint32_t* b) {
    asm volatile("mma.sync.aligned.m16n8k16.row.col.f32.bf16.bf16.f32 "
        "{%0,%1,%2,%3}, {%4,%5,%6,%7}, {%8,%9}, {%0,%1,%2,%3};"
        : "+f"(c[0]), "+f"(c[1]), "+f"(c[2]), "+f"(c[3])
        : "r"(a[0]), "r"(a[1]), "r"(a[2]), "r"(a[3]), "r"(b[0]), "r"(b[1]));
}

// ---------------- mask canonicalization (unchanged, proven) ----------------
__global__ void mask_sniff(const uint8_t* __restrict__ m) {
    __shared__ unsigned r1[256], r3[256];
    unsigned o1 = 0, o3 = 0;
    const uint32_t* w = (const uint32_t*)m;
    for (int i = threadIdx.x; i < (BB*TT)/4; i += 256) {
        uint32_t v = w[i];
        o1 |= (v >> 8) & 0xFFu; o3 |= (v >> 24) & 0xFFu;
    }
    r1[threadIdx.x] = o1; r3[threadIdx.x] = o3;
    __syncthreads();
    for (int s = 128; s; s >>= 1) {
        if (threadIdx.x < s) { r1[threadIdx.x] |= r1[threadIdx.x+s]; r3[threadIdx.x] |= r3[threadIdx.x+s]; }
        __syncthreads();
    }
    if (threadIdx.x == 0) g_mask_kind = r1[0] ? 1 : (r3[0] ? 2 : 0);
}
__global__ void mask_expand(const void* __restrict__ m) {
    int s = blockIdx.x * 256 + threadIdx.x;
    if (s >= BB*TT) return;
    int kind = g_mask_kind;
    float v;
    if (kind == 1)      v = ((const uint8_t*)m)[s] ? 1.0f : 0.0f;
    else if (kind == 2) v = (((const float*)m)[s] != 0.0f) ? 1.0f : 0.0f;
    else                v = ((const int*)m)[s] ? 1.0f : 0.0f;
    g_mask[s] = v;
}

// ---------------- prep: split x and W into bf16 hi/lo ----------------
__global__ __launch_bounds__(256) void prep_kernel(
    const float* __restrict__ x,  const float* __restrict__ Wq,
    const float* __restrict__ Wk, const float* __restrict__ Wv)
{
    const int y = blockIdx.y;
    const size_t i = (size_t)blockIdx.x * 256 + threadIdx.x;   // float4 index
    const float* src; __nv_bfloat16 *dh, *dl; size_t n4;
    if (y == 0) { src = x; dh = g_x_hi; dl = g_x_lo; n4 = (size_t)BB*TT*DD/4; }
    else {
        src = (y == 1) ? Wq : ((y == 2) ? Wk : Wv);
        dh = g_w_hi + (size_t)(y-1)*QD*DD; dl = g_w_lo + (size_t)(y-1)*QD*DD;
        n4 = (size_t)QD*DD/4;
    }
    if (i >= n4) return;
    float4 v = ((const float4*)src)[i];
    uint32_t h01, l01, h23, l23;
    split2(v.x, v.y, h01, l01);
    split2(v.z, v.w, h23, l23);
    ((uint2*)dh)[i] = make_uint2(h01, h23);
    ((uint2*)dl)[i] = make_uint2(l01, l23);
}

// ---------------- projection GEMM (bf16x3 mma.sync) ----------------
// grid (128 m-tiles, 3 ops), 256 thr. CTA tile 128m x 128n, BK=64.
// smem: AH/AL [128][64] bf16 (128B rows), BH/BL same. XOR-swizzled.
#define PJ_AH 0
#define PJ_AL 16384
#define PJ_BH 32768
#define PJ_BL 49152
#define PJ_SMEM (65536 + 1024)

__global__ __launch_bounds__(256, 1) void proj_kernel()
{
    extern __shared__ char smraw[];
    char* sp = (char*)(((uintptr_t)smraw + 1023) & ~(uintptr_t)1023);
    uint32_t sb = smem_u32(sp);
    const int tid = threadIdx.x, lane = tid & 31, w = tid >> 5;
    const int m0 = blockIdx.x * 128, z = blockIdx.y;
    const int wm = w & 3, wn = w >> 2;
    const int mrow0 = wm * 32, ncol0 = wn * 64;

    const __nv_bfloat16* xh = g_x_hi;
    const __nv_bfloat16* xl = g_x_lo;
    const __nv_bfloat16* wh = g_w_hi + (size_t)z*QD*DD;
    const __nv_bfloat16* wl = g_w_lo + (size_t)z*QD*DD;

    // per-thread ldmatrix address components
    const int mat = lane >> 3;
    const uint32_t xorv = (uint32_t)(lane & 7) << 4;
    const int rA = (mat & 1) * 8 + (lane & 7);   // A frag rows
    const int cA = (mat >> 1) * 16;              // A frag col bytes
    const int rB = (mat >> 1) * 8 + (lane & 7);  // B frag rows
    const int cB = (mat & 1) * 16;               // B frag col bytes

    float C[2][8][4] = {};

    for (int c = 0; c < 16; c++) {
        __syncthreads();
        const int k0g = c * 64;
        // stage A (x) and B (W) hi/lo tiles: 1024 uint4 each array, 4/thread
        #pragma unroll
        for (int r = 0; r < 4; r++) {
            int idx = tid + r * 256;
            int row = idx >> 3, ci = idx & 7;
            uint32_t cb = (uint32_t)ci * 16;
            uint32_t doff = (uint32_t)row * 128 + (cb ^ ((uint32_t)(row & 7) << 4));
            *(uint4*)(sp + PJ_AH + doff) = ((const uint4*)(xh + (size_t)(m0+row)*DD + k0g))[ci];
            *(uint4*)(sp + PJ_AL + doff) = ((const uint4*)(xl + (size_t)(m0+row)*DD + k0g))[ci];
            *(uint4*)(sp + PJ_BH + doff) = ((const uint4*)(wh + (size_t)row*DD + k0g))[ci];
            *(uint4*)(sp + PJ_BL + doff) = ((const uint4*)(wl + (size_t)row*DD + k0g))[ci];
        }
        __syncthreads();

        #pragma unroll
        for (int ks = 0; ks < 4; ks++) {
            const int k0 = ks * 16;
            uint32_t ah[2][4], al[2][4];
            #pragma unroll
            for (int mt = 0; mt < 2; mt++) {
                uint32_t aoff = (uint32_t)(mrow0 + mt*16 + rA) * 128 + (((uint32_t)(k0*2 + cA)) ^ xorv);
                ldm4(ah[mt], sb + PJ_AH + aoff);
                ldm4(al[mt], sb + PJ_AL + aoff);
            }
            #pragma unroll
            for (int nt2 = 0; nt2 < 4; nt2++) {
                const int n0 = ncol0 + nt2 * 16;
                uint32_t boff = (uint32_t)(n0 + rB) * 128 + (((uint32_t)(k0*2 + cB)) ^ xorv);
                uint32_t bh[4], bl[4];
                ldm4(bh, sb + PJ_BH + boff);
                ldm4(bl, sb + PJ_BL + boff);
                #pragma unroll
                for (int mt = 0; mt < 2; mt++) {
                    mma_bf16(C[mt][nt2*2],   ah[mt], bh);
                    mma_bf16(C[mt][nt2*2],   ah[mt], bl);
                    mma_bf16(C[mt][nt2*2],   al[mt], bh);
                    mma_bf16(C[mt][nt2*2+1], ah[mt], bh + 2);
                    mma_bf16(C[mt][nt2*2+1], ah[mt], bl + 2);
                    mma_bf16(C[mt][nt2*2+1], al[mt], bh + 2);
                }
            }
        }
    }

    // epilogue: split to hi/lo bf16 and store row-major [m][n]
    __nv_bfloat16 *dh, *dl;
    if (z == 0)      { dh = g_q_hi; dl = g_q_lo; }
    else if (z == 1) { dh = g_k_hi; dl = g_k_lo; }
    else             { dh = g_v_hi; dl = g_v_lo; }
    const int r = lane >> 2, c2 = 2 * (lane & 3);
    #pragma unroll
    for (int mt = 0; mt < 2; mt++) {
        #pragma unroll
        for (int nt = 0; nt < 8; nt++) {
            int cc = ncol0 + nt * 8 + c2;
            size_t mg0 = (size_t)(m0 + mrow0 + mt*16 + r);
            uint32_t h, l;
            split2(C[mt][nt][0], C[mt][nt][1], h, l);
            *(uint32_t*)(dh + mg0*QD + cc) = h;
            *(uint32_t*)(dl + mg0*QD + cc) = l;
            split2(C[mt][nt][2], C[mt][nt][3], h, l);
            *(uint32_t*)(dh + (mg0+8)*QD + cc) = h;
            *(uint32_t*)(dl + (mg0+8)*QD + cc) = l;
        }
    }
}

// ---------------- flash attention (bf16x3 mma.sync) ----------------
// grid (16 q-tiles, 8 batches), 256 thr (8 warps x 16 q-rows).
// smem: QH/QL/KH/KL/VH/VL [128][128] bf16 (256B rows, swizzled) + mask.
#define AT_QH 0
#define AT_QL 32768
#define AT_KH 65536
#define AT_KL 98304
#define AT_VH 131072
#define AT_VL 163840
#define AT_MK 196608
#define AT_SMEM (196608 + 512 + 1024)

__global__ __launch_bounds__(256, 1) void attn_kernel(float* __restrict__ out)
{
    extern __shared__ char smraw[];
    char* sp = (char*)(((uintptr_t)smraw + 1023) & ~(uintptr_t)1023);
    uint32_t sb = smem_u32(sp);
    float* mkS = (float*)(sp + AT_MK);
    const int tid = threadIdx.x, lane = tid & 31, w = tid >> 5;
    const int b = blockIdx.y, t0 = blockIdx.x * 128;
    const int m0w = w * 16;

    const int mat = lane >> 3;
    const uint32_t xorv = (uint32_t)(lane & 7) << 4;
    const int rA = (mat & 1) * 8 + (lane & 7);
    const int cA = (mat >> 1) * 16;
    const int rB = (mat >> 1) * 8 + (lane & 7);
    const int cB = (mat & 1) * 16;

    // stage Q tile (hi/lo)
    {
        const uint4* qh = (const uint4*)(g_q_hi + (size_t)(b*TT + t0) * QD);
        const uint4* ql = (const uint4*)(g_q_lo + (size_t)(b*TT + t0) * QD);
        #pragma unroll
        for (int r = 0; r < 8; r++) {
            int idx = tid + r * 256;
            int row = idx >> 4;
            uint32_t cb = (uint32_t)(idx & 15) * 16;
            uint32_t doff = (uint32_t)row * 256 + (cb ^ ((uint32_t)(row & 7) << 4));
            *(uint4*)(sp + AT_QH + doff) = qh[idx];
            *(uint4*)(sp + AT_QL + doff) = ql[idx];
        }
    }

    float O[16][4] = {};
    float m0r = -1.0e30f, m1r = -1.0e30f, s0r = 0.0f, s1r = 0.0f;
    const int c2 = 2 * (lane & 3);

    for (int it = 0; it < 16; it++) {
        __syncthreads();   // previous iteration done with K/V smem
        const int s0g = it * 128;
        if (tid < 128) mkS[tid] = g_mask[b*TT + s0g + tid];
        {
            const uint4* kh = (const uint4*)(g_k_hi + (size_t)(b*TT + s0g) * QD);
            const uint4* kl = (const uint4*)(g_k_lo + (size_t)(b*TT + s0g) * QD);
            const uint4* vh = (const uint4*)(g_v_hi + (size_t)(b*TT + s0g) * QD);
            const uint4* vl = (const uint4*)(g_v_lo + (size_t)(b*TT + s0g) * QD);
            #pragma unroll
            for (int r = 0; r < 8; r++) {
                int idx = tid + r * 256;
                int row = idx >> 4;
                uint32_t cb = (uint32_t)(idx & 15) * 16;
                uint32_t doff = (uint32_t)row * 256 + (cb ^ ((uint32_t)(row & 7) << 4));
                *(uint4*)(sp + AT_KH + doff) = kh[idx];
                *(uint4*)(sp + AT_KL + doff) = kl[idx];
                *(uint4*)(sp + AT_VH + doff) = vh[idx];
                *(uint4*)(sp + AT_VL + doff) = vl[idx];
            }
        }
        __syncthreads();

        // S = Q K^T  (128 s-cols in registers per warp)
        float S[16][4] = {};
        #pragma unroll
        for (int ks = 0; ks < 8; ks++) {
            const int k0 = ks * 16;
            uint32_t aqh[4], aql[4];
            uint32_t aoff = (uint32_t)(m0w + rA) * 256 + (((uint32_t)(k0*2 + cA)) ^ xorv);
            ldm4(aqh, sb + AT_QH + aoff);
            ldm4(aql, sb + AT_QL + aoff);
            #pragma unroll
            for (int nt2 = 0; nt2 < 8; nt2++) {
                const int n0 = nt2 * 16;
                uint32_t boff = (uint32_t)(n0 + rB) * 256 + (((uint32_t)(k0*2 + cB)) ^ xorv);
                uint32_t bh[4], bl[4];
                ldm4(bh, sb + AT_KH + boff);
                ldm4(bl, sb + AT_KL + boff);
                mma_bf16(S[nt2*2],   aqh, bh);
                mma_bf16(S[nt2*2],   aqh, bl);
                mma_bf16(S[nt2*2],   aql, bh);
                mma_bf16(S[nt2*2+1], aqh, bh + 2);
                mma_bf16(S[nt2*2+1], aqh, bl + 2);
                mma_bf16(S[nt2*2+1], aql, bh + 2);
            }
        }

        // masked online softmax (rows r=lane>>2 and r+8)
        float mx0 = -3.0e38f, mx1 = -3.0e38f;
        #pragma unroll
        for (int nt = 0; nt < 16; nt++) {
            float k0m = mkS[nt*8 + c2], k1m = mkS[nt*8 + c2 + 1];
            S[nt][0] = (k0m != 0.0f) ? S[nt][0] : -3.0e38f;
            S[nt][1] = (k1m != 0.0f) ? S[nt][1] : -3.0e38f;
            S[nt][2] = (k0m != 0.0f) ? S[nt][2] : -3.0e38f;
            S[nt][3] = (k1m != 0.0f) ? S[nt][3] : -3.0e38f;
            mx0 = fmaxf(mx0, fmaxf(S[nt][0], S[nt][1]));
            mx1 = fmaxf(mx1, fmaxf(S[nt][2], S[nt][3]));
        }
        mx0 = fmaxf(mx0, __shfl_xor_sync(0xffffffffu, mx0, 1));
        mx0 = fmaxf(mx0, __shfl_xor_sync(0xffffffffu, mx0, 2));
        mx1 = fmaxf(mx1, __shfl_xor_sync(0xffffffffu, mx1, 1));
        mx1 = fmaxf(mx1, __shfl_xor_sync(0xffffffffu, mx1, 2));
        float mn0 = fmaxf(m0r, mx0), mn1 = fmaxf(m1r, mx1);
        float sc0 = __expf(m0r - mn0), sc1 = __expf(m1r - mn1);
        float sum0 = 0.0f, sum1 = 0.0f;
        #pragma unroll
        for (int nt = 0; nt < 16; nt++) {
            S[nt][0] = __expf(S[nt][0] - mn0);
            S[nt][1] = __expf(S[nt][1] - mn0);
            S[nt][2] = __expf(S[nt][2] - mn1);
            S[nt][3] = __expf(S[nt][3] - mn1);
            sum0 += S[nt][0] + S[nt][1];
            sum1 += S[nt][2] + S[nt][3];
        }
        sum0 += __shfl_xor_sync(0xffffffffu, sum0, 1);
        sum0 += __shfl_xor_sync(0xffffffffu, sum0, 2);
        sum1 += __shfl_xor_sync(0xffffffffu, sum1, 1);
        sum1 += __shfl_xor_sync(0xffffffffu, sum1, 2);
        s0r = s0r * sc0 + sum0;  s1r = s1r * sc1 + sum1;
        m0r = mn0;  m1r = mn1;
        #pragma unroll
        for (int nt = 0; nt < 16; nt++) {
            O[nt][0] *= sc0; O[nt][1] *= sc0;
            O[nt][2] *= sc1; O[nt][3] *= sc1;
        }

        // O += P V   (P fragments rebuilt from S registers, V via ldmatrix.trans)
        #pragma unroll
        for (int ks = 0; ks < 8; ks++) {
            uint32_t ah[4], al[4];
            split2(S[2*ks][0],   S[2*ks][1],   ah[0], al[0]);
            split2(S[2*ks][2],   S[2*ks][3],   ah[1], al[1]);
            split2(S[2*ks+1][0], S[2*ks+1][1], ah[2], al[2]);
            split2(S[2*ks+1][2], S[2*ks+1][3], ah[3], al[3]);
            const int sv0 = ks * 16;
            #pragma unroll
            for (int nt2 = 0; nt2 < 8; nt2++) {
                const int d0 = nt2 * 16;
                uint32_t voff = (uint32_t)(sv0 + rA) * 256 + (((uint32_t)(d0*2 + cA)) ^ xorv);
                uint32_t bvh[4], bvl[4];
                ldm4t(bvh, sb + AT_VH + voff);
                ldm4t(bvl, sb + AT_VL + voff);
                mma_bf16(O[nt2*2],   ah, bvh);
                mma_bf16(O[nt2*2],   ah, bvl);
                mma_bf16(O[nt2*2],   al, bvh);
                mma_bf16(O[nt2*2+1], ah, bvh + 2);
                mma_bf16(O[nt2*2+1], ah, bvl + 2);
                mma_bf16(O[nt2*2+1], al, bvh + 2);
            }
        }
    }

    // normalize + store
    const float inv0 = (s0r > 0.0f) ? 1.0f / s0r : 0.0f;
    const float inv1 = (s1r > 0.0f) ? 1.0f / s1r : 0.0f;
    const size_t row0 = (size_t)b*TT + t0 + m0w + (lane >> 2);
    #pragma unroll
    for (int nt = 0; nt < 16; nt++) {
        int col = nt * 8 + c2;
        *(float2*)(out + row0*QD + col)     = make_float2(O[nt][0]*inv0, O[nt][1]*inv0);
        *(float2*)(out + (row0+8)*QD + col) = make_float2(O[nt][2]*inv1, O[nt][3]*inv1);
    }
}

// ---------------- launch ----------------
extern "C" void kernel_launch(void* const* d_in, const int* in_sizes, int n_in,
                              void* d_out, int out_size)
{
    const float* x  = (const float*)d_in[0];
    const void*  mk = d_in[1];
    const float* Wq = (const float*)d_in[2];
    const float* Wk = (const float*)d_in[3];
    const float* Wv = (const float*)d_in[4];
    float* out = (float*)d_out;
    (void)in_sizes; (void)n_in; (void)out_size;

    mask_sniff<<<1, 256>>>((const uint8_t*)mk);
    mask_expand<<<(BB*TT + 255)/256, 256>>>(mk);

    dim3 gp((BB*TT*DD/4 + 255)/256, 4);
    prep_kernel<<<gp, 256>>>(x, Wq, Wk, Wv);

    cudaFuncSetAttribute(proj_kernel, cudaFuncAttributeMaxDynamicSharedMemorySize, PJ_SMEM);
    cudaFuncSetAttribute(attn_kernel, cudaFuncAttributeMaxDynamicSharedMemorySize, AT_SMEM);

    dim3 g1(128, 3);
    proj_kernel<<<g1, 256, PJ_SMEM>>>();
    dim3 g2(16, 8);
    attn_kernel<<<g2, 256, AT_SMEM>>>(out);
}

// round 10
// speedup vs baseline: 7.5027x; 2.2350x over previous
#include <cuda_runtime.h>
#include <cuda_bf16.h>
#include <cstdint>

#define BB 8
#define TT 2048
#define DD 1024
#define QD 128

// ---------------- global scratch ----------------
__device__ __nv_bfloat16 g_x_hi[(size_t)BB*TT*DD];
__device__ __nv_bfloat16 g_x_lo[(size_t)BB*TT*DD];
__device__ __nv_bfloat16 g_w_hi[3*QD*DD];
__device__ __nv_bfloat16 g_w_lo[3*QD*DD];
__device__ __nv_bfloat16 g_q_hi[BB*TT*QD];
__device__ __nv_bfloat16 g_q_lo[BB*TT*QD];
__device__ __nv_bfloat16 g_k_hi[BB*TT*QD];
__device__ __nv_bfloat16 g_k_lo[BB*TT*QD];
__device__ __nv_bfloat16 g_v_hi[BB*TT*QD];           // row-major [b][t][d]
__device__ __nv_bfloat16 g_v_lo[BB*TT*QD];
__device__ float g_mask[BB*TT];
__device__ int   g_mask_kind;

// ---------------- helpers ----------------
__device__ __forceinline__ uint32_t smem_u32(const void* p) {
    uint32_t a;
    asm("{ .reg .u64 t; cvta.to.shared.u64 t, %1; cvt.u32.u64 %0, t; }" : "=r"(a) : "l"(p));
    return a;
}
__device__ __forceinline__ uint32_t pk(__nv_bfloat16 a, __nv_bfloat16 b) {
    return (uint32_t)__bfloat16_as_ushort(a) | ((uint32_t)__bfloat16_as_ushort(b) << 16);
}
__device__ __forceinline__ void split2(float a, float b, uint32_t& h, uint32_t& l) {
    __nv_bfloat16 ha = __float2bfloat16_rn(a);
    __nv_bfloat16 hb = __float2bfloat16_rn(b);
    __nv_bfloat16 la = __float2bfloat16_rn(a - __bfloat162float(ha));
    __nv_bfloat16 lb = __float2bfloat16_rn(b - __bfloat162float(hb));
    h = pk(ha, hb); l = pk(la, lb);
}
__device__ __forceinline__ void ldm4(uint32_t r[4], uint32_t a) {
    asm volatile("ldmatrix.sync.aligned.m8n8.x4.shared.b16 {%0,%1,%2,%3}, [%4];"
        : "=r"(r[0]), "=r"(r[1]), "=r"(r[2]), "=r"(r[3]) : "r"(a));
}
__device__ __forceinline__ void ldm4t(uint32_t r[4], uint32_t a) {
    asm volatile("ldmatrix.sync.aligned.m8n8.x4.trans.shared.b16 {%0,%1,%2,%3}, [%4];"
        : "=r"(r[0]), "=r"(r[1]), "=r"(r[2]), "=r"(r[3]) : "r"(a));
}
__device__ __forceinline__ void mma_bf16(float* c, const uint32_t* a, const uint32_t* b) {
    asm volatile("mma.sync.aligned.m16n8k16.row.col.f32.bf16.bf16.f32 "
        "{%0,%1,%2,%3}, {%4,%5,%6,%7}, {%8,%9}, {%0,%1,%2,%3};"
        : "+f"(c[0]), "+f"(c[1]), "+f"(c[2]), "+f"(c[3])
        : "r"(a[0]), "r"(a[1]), "r"(a[2]), "r"(a[3]), "r"(b[0]), "r"(b[1]));
}
__device__ __forceinline__ void cp16(uint32_t dst, const void* src) {
    asm volatile("cp.async.cg.shared.global [%0], [%1], 16;"
        :: "r"(dst), "l"(__cvta_generic_to_global(src)) : "memory");
}
#define CP_COMMIT() asm volatile("cp.async.commit_group;" ::: "memory")
#define CP_WAIT(n)  asm volatile("cp.async.wait_group %0;" :: "n"(n) : "memory")

// ---------------- mask canonicalization (proven) ----------------
__global__ void mask_sniff(const uint8_t* __restrict__ m) {
    __shared__ unsigned r1[256], r3[256];
    unsigned o1 = 0, o3 = 0;
    const uint32_t* w = (const uint32_t*)m;
    for (int i = threadIdx.x; i < (BB*TT)/4; i += 256) {
        uint32_t v = w[i];
        o1 |= (v >> 8) & 0xFFu; o3 |= (v >> 24) & 0xFFu;
    }
    r1[threadIdx.x] = o1; r3[threadIdx.x] = o3;
    __syncthreads();
    for (int s = 128; s; s >>= 1) {
        if (threadIdx.x < s) { r1[threadIdx.x] |= r1[threadIdx.x+s]; r3[threadIdx.x] |= r3[threadIdx.x+s]; }
        __syncthreads();
    }
    if (threadIdx.x == 0) g_mask_kind = r1[0] ? 1 : (r3[0] ? 2 : 0);
}
__global__ void mask_expand(const void* __restrict__ m) {
    int s = blockIdx.x * 256 + threadIdx.x;
    if (s >= BB*TT) return;
    int kind = g_mask_kind;
    float v;
    if (kind == 1)      v = ((const uint8_t*)m)[s] ? 1.0f : 0.0f;
    else if (kind == 2) v = (((const float*)m)[s] != 0.0f) ? 1.0f : 0.0f;
    else                v = ((const int*)m)[s] ? 1.0f : 0.0f;
    g_mask[s] = v;
}

// ---------------- prep: split x and W into bf16 hi/lo ----------------
__global__ __launch_bounds__(256) void prep_kernel(
    const float* __restrict__ x,  const float* __restrict__ Wq,
    const float* __restrict__ Wk, const float* __restrict__ Wv)
{
    const int y = blockIdx.y;
    const size_t i = (size_t)blockIdx.x * 256 + threadIdx.x;
    const float* src; __nv_bfloat16 *dh, *dl; size_t n4;
    if (y == 0) { src = x; dh = g_x_hi; dl = g_x_lo; n4 = (size_t)BB*TT*DD/4; }
    else {
        src = (y == 1) ? Wq : ((y == 2) ? Wk : Wv);
        dh = g_w_hi + (size_t)(y-1)*QD*DD; dl = g_w_lo + (size_t)(y-1)*QD*DD;
        n4 = (size_t)QD*DD/4;
    }
    if (i >= n4) return;
    float4 v = ((const float4*)src)[i];
    uint32_t h01, l01, h23, l23;
    split2(v.x, v.y, h01, l01);
    split2(v.z, v.w, h23, l23);
    ((uint2*)dh)[i] = make_uint2(h01, h23);
    ((uint2*)dl)[i] = make_uint2(l01, l23);
}

// ---------------- projection GEMM (bf16x3, cp.async 2-stage) ----------------
// grid (128 m-tiles, 3 ops), 256 thr. CTA tile 128m x 128n, BK=64.
#define PJ_AH 0
#define PJ_AL 16384
#define PJ_BH 32768
#define PJ_BL 49152
#define PJ_STAGE 65536
#define PJ_SMEM (2*PJ_STAGE + 1024)

__global__ __launch_bounds__(256, 1) void proj_kernel()
{
    extern __shared__ char smraw[];
    char* sp = (char*)(((uintptr_t)smraw + 1023) & ~(uintptr_t)1023);
    uint32_t sb = smem_u32(sp);
    const int tid = threadIdx.x, lane = tid & 31, w = tid >> 5;
    const int m0 = blockIdx.x * 128, z = blockIdx.y;
    const int wm = w & 3, wn = w >> 2;
    const int mrow0 = wm * 32, ncol0 = wn * 64;

    const __nv_bfloat16* xh = g_x_hi;
    const __nv_bfloat16* xl = g_x_lo;
    const __nv_bfloat16* wh = g_w_hi + (size_t)z*QD*DD;
    const __nv_bfloat16* wl = g_w_lo + (size_t)z*QD*DD;

    const int mat = lane >> 3;
    const uint32_t xorv = (uint32_t)(lane & 7) << 4;
    const int rA = (mat & 1) * 8 + (lane & 7);
    const int cA = (mat >> 1) * 16;
    const int rB = (mat >> 1) * 8 + (lane & 7);
    const int cB = (mat & 1) * 16;

    // per-thread staging address components (4 uint4 per array per stage)
    const int srow = tid >> 3, sci = tid & 7;          // base: rows tid>>3 step 32
    float C[2][8][4] = {};

    // stage chunk c into buffer (c&1)
    #define PJ_STAGE_CHUNK(c) do {                                              \
        const int _k0 = (c) * 64;                                               \
        uint32_t _bb = sb + (uint32_t)((c) & 1) * PJ_STAGE;                     \
        _Pragma("unroll")                                                       \
        for (int _r = 0; _r < 4; _r++) {                                        \
            int _row = srow + _r * 32;                                          \
            uint32_t _doff = (uint32_t)_row * 128 +                             \
                (((uint32_t)sci * 16) ^ ((uint32_t)(_row & 7) << 4));           \
            const size_t _go = (size_t)(m0 + _row) * DD + _k0 + sci * 8;        \
            const size_t _gw = (size_t)_row * DD + _k0 + sci * 8;               \
            cp16(_bb + PJ_AH + _doff, xh + _go);                                \
            cp16(_bb + PJ_AL + _doff, xl + _go);                                \
            cp16(_bb + PJ_BH + _doff, wh + _gw);                                \
            cp16(_bb + PJ_BL + _doff, wl + _gw);                                \
        } } while (0)

    PJ_STAGE_CHUNK(0); CP_COMMIT();

    for (int c = 0; c < 16; c++) {
        if (c + 1 < 16) { PJ_STAGE_CHUNK(c + 1); CP_COMMIT(); CP_WAIT(1); }
        else            { CP_WAIT(0); }
        __syncthreads();
        const uint32_t bb = sb + (uint32_t)(c & 1) * PJ_STAGE;

        #pragma unroll
        for (int ks = 0; ks < 4; ks++) {
            const int k0 = ks * 16;
            uint32_t ah[2][4], al[2][4];
            #pragma unroll
            for (int mt = 0; mt < 2; mt++) {
                uint32_t aoff = (uint32_t)(mrow0 + mt*16 + rA) * 128 + (((uint32_t)(k0*2 + cA)) ^ xorv);
                ldm4(ah[mt], bb + PJ_AH + aoff);
                ldm4(al[mt], bb + PJ_AL + aoff);
            }
            #pragma unroll
            for (int nt2 = 0; nt2 < 4; nt2++) {
                const int n0 = ncol0 + nt2 * 16;
                uint32_t boff = (uint32_t)(n0 + rB) * 128 + (((uint32_t)(k0*2 + cB)) ^ xorv);
                uint32_t bh[4], bl[4];
                ldm4(bh, bb + PJ_BH + boff);
                ldm4(bl, bb + PJ_BL + boff);
                #pragma unroll
                for (int mt = 0; mt < 2; mt++) {
                    mma_bf16(C[mt][nt2*2],   ah[mt], bh);
                    mma_bf16(C[mt][nt2*2],   ah[mt], bl);
                    mma_bf16(C[mt][nt2*2],   al[mt], bh);
                    mma_bf16(C[mt][nt2*2+1], ah[mt], bh + 2);
                    mma_bf16(C[mt][nt2*2+1], ah[mt], bl + 2);
                    mma_bf16(C[mt][nt2*2+1], al[mt], bh + 2);
                }
            }
        }
        __syncthreads();
    }

    // epilogue: split to hi/lo bf16, store row-major
    __nv_bfloat16 *dh, *dl;
    if (z == 0)      { dh = g_q_hi; dl = g_q_lo; }
    else if (z == 1) { dh = g_k_hi; dl = g_k_lo; }
    else             { dh = g_v_hi; dl = g_v_lo; }
    const int r = lane >> 2, c2 = 2 * (lane & 3);
    #pragma unroll
    for (int mt = 0; mt < 2; mt++) {
        #pragma unroll
        for (int nt = 0; nt < 8; nt++) {
            int cc = ncol0 + nt * 8 + c2;
            size_t mg0 = (size_t)(m0 + mrow0 + mt*16 + r);
            uint32_t h, l;
            split2(C[mt][nt][0], C[mt][nt][1], h, l);
            *(uint32_t*)(dh + mg0*QD + cc) = h;
            *(uint32_t*)(dl + mg0*QD + cc) = l;
            split2(C[mt][nt][2], C[mt][nt][3], h, l);
            *(uint32_t*)(dh + (mg0+8)*QD + cc) = h;
            *(uint32_t*)(dl + (mg0+8)*QD + cc) = l;
        }
    }
}

// ---------------- flash attention (bf16x3, phase-pipelined cp.async) ----------------
// grid (16 q-tiles, 8 batches), 256 thr. K(it+1) loads overlap PV(it);
// V(it) loads overlap S(it). FIFO group order guarantees wait_group(1) = oldest done.
#define AT_QH 0
#define AT_QL 32768
#define AT_KH 65536
#define AT_KL 98304
#define AT_VH 131072
#define AT_VL 163840
#define AT_MK 196608
#define AT_SMEM (196608 + 512 + 1024)

__global__ __launch_bounds__(256, 1) void attn_kernel(float* __restrict__ out)
{
    extern __shared__ char smraw[];
    char* sp = (char*)(((uintptr_t)smraw + 1023) & ~(uintptr_t)1023);
    uint32_t sb = smem_u32(sp);
    float* mkS = (float*)(sp + AT_MK);
    const int tid = threadIdx.x, lane = tid & 31, w = tid >> 5;
    const int b = blockIdx.y, t0 = blockIdx.x * 128;
    const int m0w = w * 16;

    const int mat = lane >> 3;
    const uint32_t xorv = (uint32_t)(lane & 7) << 4;
    const int rA = (mat & 1) * 8 + (lane & 7);
    const int cA = (mat >> 1) * 16;
    const int rB = (mat >> 1) * 8 + (lane & 7);
    const int cB = (mat & 1) * 16;

    const int srow = tid >> 4, sci = tid & 15;   // staging: rows tid>>4 step 16

    #define AT_ISSUE_K(it) do {                                                 \
        const int _s0 = (it) * 128;                                             \
        _Pragma("unroll")                                                       \
        for (int _r = 0; _r < 8; _r++) {                                        \
            int _row = srow + _r * 16;                                          \
            uint32_t _doff = (uint32_t)_row * 256 +                             \
                (((uint32_t)sci * 16) ^ ((uint32_t)(_row & 7) << 4));           \
            const size_t _g = (size_t)(b*TT + _s0 + _row) * QD + sci * 8;       \
            cp16(sb + AT_KH + _doff, g_k_hi + _g);                              \
            cp16(sb + AT_KL + _doff, g_k_lo + _g);                              \
        }                                                                       \
        if (tid < 32) cp16(sb + AT_MK + tid*16, g_mask + b*TT + _s0 + tid*4);   \
    } while (0)

    #define AT_ISSUE_V(it) do {                                                 \
        const int _s0 = (it) * 128;                                             \
        _Pragma("unroll")                                                       \
        for (int _r = 0; _r < 8; _r++) {                                        \
            int _row = srow + _r * 16;                                          \
            uint32_t _doff = (uint32_t)_row * 256 +                             \
                (((uint32_t)sci * 16) ^ ((uint32_t)(_row & 7) << 4));           \
            const size_t _g = (size_t)(b*TT + _s0 + _row) * QD + sci * 8;       \
            cp16(sb + AT_VH + _doff, g_v_hi + _g);                              \
            cp16(sb + AT_VL + _doff, g_v_lo + _g);                              \
        } } while (0)

    AT_ISSUE_K(0); CP_COMMIT();      // group K0 (+mask)
    AT_ISSUE_V(0); CP_COMMIT();      // group V0

    // stage Q tile (regular loads, once)
    {
        const uint4* qh = (const uint4*)(g_q_hi + (size_t)(b*TT + t0) * QD);
        const uint4* ql = (const uint4*)(g_q_lo + (size_t)(b*TT + t0) * QD);
        #pragma unroll
        for (int r = 0; r < 8; r++) {
            int idx = tid + r * 256;
            int row = idx >> 4;
            uint32_t cb = (uint32_t)(idx & 15) * 16;
            uint32_t doff = (uint32_t)row * 256 + (cb ^ ((uint32_t)(row & 7) << 4));
            *(uint4*)(sp + AT_QH + doff) = qh[idx];
            *(uint4*)(sp + AT_QL + doff) = ql[idx];
        }
    }

    float O[16][4] = {};
    float m0r = -1.0e30f, m1r = -1.0e30f, s0r = 0.0f, s1r = 0.0f;
    const int c2 = 2 * (lane & 3);

    for (int it = 0; it < 16; it++) {
        CP_WAIT(1);                  // K(it) done (V(it) may be in flight)
        __syncthreads();

        // S = Q K^T
        float S[16][4] = {};
        #pragma unroll
        for (int ks = 0; ks < 8; ks++) {
            const int k0 = ks * 16;
            uint32_t aqh[4], aql[4];
            uint32_t aoff = (uint32_t)(m0w + rA) * 256 + (((uint32_t)(k0*2 + cA)) ^ xorv);
            ldm4(aqh, sb + AT_QH + aoff);
            ldm4(aql, sb + AT_QL + aoff);
            #pragma unroll
            for (int nt2 = 0; nt2 < 8; nt2++) {
                const int n0 = nt2 * 16;
                uint32_t boff = (uint32_t)(n0 + rB) * 256 + (((uint32_t)(k0*2 + cB)) ^ xorv);
                uint32_t bh[4], bl[4];
                ldm4(bh, sb + AT_KH + boff);
                ldm4(bl, sb + AT_KL + boff);
                mma_bf16(S[nt2*2],   aqh, bh);
                mma_bf16(S[nt2*2],   aqh, bl);
                mma_bf16(S[nt2*2],   aql, bh);
                mma_bf16(S[nt2*2+1], aqh, bh + 2);
                mma_bf16(S[nt2*2+1], aqh, bl + 2);
                mma_bf16(S[nt2*2+1], aql, bh + 2);
            }
        }

        // masked online softmax (rows lane>>2 and +8)
        float mx0 = -3.0e38f, mx1 = -3.0e38f;
        #pragma unroll
        for (int nt = 0; nt < 16; nt++) {
            float k0m = mkS[nt*8 + c2], k1m = mkS[nt*8 + c2 + 1];
            S[nt][0] = (k0m != 0.0f) ? S[nt][0] : -3.0e38f;
            S[nt][1] = (k1m != 0.0f) ? S[nt][1] : -3.0e38f;
            S[nt][2] = (k0m != 0.0f) ? S[nt][2] : -3.0e38f;
            S[nt][3] = (k1m != 0.0f) ? S[nt][3] : -3.0e38f;
            mx0 = fmaxf(mx0, fmaxf(S[nt][0], S[nt][1]));
            mx1 = fmaxf(mx1, fmaxf(S[nt][2], S[nt][3]));
        }
        mx0 = fmaxf(mx0, __shfl_xor_sync(0xffffffffu, mx0, 1));
        mx0 = fmaxf(mx0, __shfl_xor_sync(0xffffffffu, mx0, 2));
        mx1 = fmaxf(mx1, __shfl_xor_sync(0xffffffffu, mx1, 1));
        mx1 = fmaxf(mx1, __shfl_xor_sync(0xffffffffu, mx1, 2));
        float mn0 = fmaxf(m0r, mx0), mn1 = fmaxf(m1r, mx1);
        float sc0 = __expf(m0r - mn0), sc1 = __expf(m1r - mn1);
        float sum0 = 0.0f, sum1 = 0.0f;
        #pragma unroll
        for (int nt = 0; nt < 16; nt++) {
            S[nt][0] = __expf(S[nt][0] - mn0);
            S[nt][1] = __expf(S[nt][1] - mn0);
            S[nt][2] = __expf(S[nt][2] - mn1);
            S[nt][3] = __expf(S[nt][3] - mn1);
            sum0 += S[nt][0] + S[nt][1];
            sum1 += S[nt][2] + S[nt][3];
        }
        sum0 += __shfl_xor_sync(0xffffffffu, sum0, 1);
        sum0 += __shfl_xor_sync(0xffffffffu, sum0, 2);
        sum1 += __shfl_xor_sync(0xffffffffu, sum1, 1);
        sum1 += __shfl_xor_sync(0xffffffffu, sum1, 2);
        s0r = s0r * sc0 + sum0;  s1r = s1r * sc1 + sum1;
        m0r = mn0;  m1r = mn1;

        __syncthreads();             // all warps done with K smem + mask
        if (it + 1 < 16) { AT_ISSUE_K(it + 1); CP_COMMIT(); CP_WAIT(1); }  // V(it) done
        else             { CP_WAIT(0); }
        __syncthreads();

        #pragma unroll
        for (int nt = 0; nt < 16; nt++) {
            O[nt][0] *= sc0; O[nt][1] *= sc0;
            O[nt][2] *= sc1; O[nt][3] *= sc1;
        }

        // O += P V (P rebuilt from S regs, V via ldmatrix.trans)
        #pragma unroll
        for (int ks = 0; ks < 8; ks++) {
            uint32_t ah[4], al[4];
            split2(S[2*ks][0],   S[2*ks][1],   ah[0], al[0]);
            split2(S[2*ks][2],   S[2*ks][3],   ah[1], al[1]);
            split2(S[2*ks+1][0], S[2*ks+1][1], ah[2], al[2]);
            split2(S[2*ks+1][2], S[2*ks+1][3], ah[3], al[3]);
            const int sv0 = ks * 16;
            #pragma unroll
            for (int nt2 = 0; nt2 < 8; nt2++) {
                const int d0 = nt2 * 16;
                uint32_t voff = (uint32_t)(sv0 + rA) * 256 + (((uint32_t)(d0*2 + cA)) ^ xorv);
                uint32_t bvh[4], bvl[4];
                ldm4t(bvh, sb + AT_VH + voff);
                ldm4t(bvl, sb + AT_VL + voff);
                mma_bf16(O[nt2*2],   ah, bvh);
                mma_bf16(O[nt2*2],   ah, bvl);
                mma_bf16(O[nt2*2],   al, bvh);
                mma_bf16(O[nt2*2+1], ah, bvh + 2);
                mma_bf16(O[nt2*2+1], ah, bvl + 2);
                mma_bf16(O[nt2*2+1], al, bvh + 2);
            }
        }
        __syncthreads();             // all warps done with V smem
        if (it + 1 < 16) { AT_ISSUE_V(it + 1); CP_COMMIT(); }
    }

    // normalize + store
    const float inv0 = (s0r > 0.0f) ? 1.0f / s0r : 0.0f;
    const float inv1 = (s1r > 0.0f) ? 1.0f / s1r : 0.0f;
    const size_t row0 = (size_t)b*TT + t0 + m0w + (lane >> 2);
    #pragma unroll
    for (int nt = 0; nt < 16; nt++) {
        int col = nt * 8 + c2;
        *(float2*)(out + row0*QD + col)     = make_float2(O[nt][0]*inv0, O[nt][1]*inv0);
        *(float2*)(out + (row0+8)*QD + col) = make_float2(O[nt][2]*inv1, O[nt][3]*inv1);
    }
}

// ---------------- launch ----------------
extern "C" void kernel_launch(void* const* d_in, const int* in_sizes, int n_in,
                              void* d_out, int out_size)
{
    const float* x  = (const float*)d_in[0];
    const void*  mk = d_in[1];
    const float* Wq = (const float*)d_in[2];
    const float* Wk = (const float*)d_in[3];
    const float* Wv = (const float*)d_in[4];
    float* out = (float*)d_out;
    (void)in_sizes; (void)n_in; (void)out_size;

    mask_sniff<<<1, 256>>>((const uint8_t*)mk);
    mask_expand<<<(BB*TT + 255)/256, 256>>>(mk);

    dim3 gp((BB*TT*DD/4 + 255)/256, 4);
    prep_kernel<<<gp, 256>>>(x, Wq, Wk, Wv);

    cudaFuncSetAttribute(proj_kernel, cudaFuncAttributeMaxDynamicSharedMemorySize, PJ_SMEM);
    cudaFuncSetAttribute(attn_kernel, cudaFuncAttributeMaxDynamicSharedMemorySize, AT_SMEM);

    dim3 g1(128, 3);
    proj_kernel<<<g1, 256, PJ_SMEM>>>();
    dim3 g2(16, 8);
    attn_kernel<<<g2, 256, AT_SMEM>>>(out);
}

// round 11
// speedup vs baseline: 7.5730x; 1.0094x over previous
#include <cuda_runtime.h>
#include <cuda_bf16.h>
#include <cstdint>

#define BB 8
#define TT 2048
#define DD 1024
#define QD 128

// ---------------- global scratch ----------------
__device__ __nv_bfloat16 g_x_hi[(size_t)BB*TT*DD];
__device__ __nv_bfloat16 g_x_lo[(size_t)BB*TT*DD];
__device__ __nv_bfloat16 g_w_hi[3*QD*DD];
__device__ __nv_bfloat16 g_w_lo[3*QD*DD];
__device__ __nv_bfloat16 g_q_hi[BB*TT*QD];
__device__ __nv_bfloat16 g_q_lo[BB*TT*QD];
__device__ __nv_bfloat16 g_k_hi[BB*TT*QD];
__device__ __nv_bfloat16 g_k_lo[BB*TT*QD];
__device__ __nv_bfloat16 g_v_hi[BB*TT*QD];           // row-major [b][t][d]
__device__ __nv_bfloat16 g_v_lo[BB*TT*QD];
__device__ float g_mask[BB*TT];
__device__ int   g_mask_kind;

// ---------------- helpers ----------------
__device__ __forceinline__ uint32_t smem_u32(const void* p) {
    uint32_t a;
    asm("{ .reg .u64 t; cvta.to.shared.u64 t, %1; cvt.u32.u64 %0, t; }" : "=r"(a) : "l"(p));
    return a;
}
__device__ __forceinline__ uint32_t pk(__nv_bfloat16 a, __nv_bfloat16 b) {
    return (uint32_t)__bfloat16_as_ushort(a) | ((uint32_t)__bfloat16_as_ushort(b) << 16);
}
__device__ __forceinline__ void split2(float a, float b, uint32_t& h, uint32_t& l) {
    __nv_bfloat16 ha = __float2bfloat16_rn(a);
    __nv_bfloat16 hb = __float2bfloat16_rn(b);
    __nv_bfloat16 la = __float2bfloat16_rn(a - __bfloat162float(ha));
    __nv_bfloat16 lb = __float2bfloat16_rn(b - __bfloat162float(hb));
    h = pk(ha, hb); l = pk(la, lb);
}
__device__ __forceinline__ void ldm4(uint32_t r[4], uint32_t a) {
    asm volatile("ldmatrix.sync.aligned.m8n8.x4.shared.b16 {%0,%1,%2,%3}, [%4];"
        : "=r"(r[0]), "=r"(r[1]), "=r"(r[2]), "=r"(r[3]) : "r"(a));
}
__device__ __forceinline__ void ldm4t(uint32_t r[4], uint32_t a) {
    asm volatile("ldmatrix.sync.aligned.m8n8.x4.trans.shared.b16 {%0,%1,%2,%3}, [%4];"
        : "=r"(r[0]), "=r"(r[1]), "=r"(r[2]), "=r"(r[3]) : "r"(a));
}
__device__ __forceinline__ void mma_bf16(float* c, const uint32_t* a, const uint32_t* b) {
    asm volatile("mma.sync.aligned.m16n8k16.row.col.f32.bf16.bf16.f32 "
        "{%0,%1,%2,%3}, {%4,%5,%6,%7}, {%8,%9}, {%0,%1,%2,%3};"
        : "+f"(c[0]), "+f"(c[1]), "+f"(c[2]), "+f"(c[3])
        : "r"(a[0]), "r"(a[1]), "r"(a[2]), "r"(a[3]), "r"(b[0]), "r"(b[1]));
}
__device__ __forceinline__ void cp16(uint32_t dst, const void* src) {
    asm volatile("cp.async.cg.shared.global [%0], [%1], 16;"
        :: "r"(dst), "l"(__cvta_generic_to_global(src)) : "memory");
}
#define CP_COMMIT() asm volatile("cp.async.commit_group;" ::: "memory")
#define CP_WAIT(n)  asm volatile("cp.async.wait_group %0;" :: "n"(n) : "memory")

// ---------------- mask canonicalization (proven) ----------------
__global__ void mask_sniff(const uint8_t* __restrict__ m) {
    __shared__ unsigned r1[256], r3[256];
    unsigned o1 = 0, o3 = 0;
    const uint32_t* w = (const uint32_t*)m;
    for (int i = threadIdx.x; i < (BB*TT)/4; i += 256) {
        uint32_t v = w[i];
        o1 |= (v >> 8) & 0xFFu; o3 |= (v >> 24) & 0xFFu;
    }
    r1[threadIdx.x] = o1; r3[threadIdx.x] = o3;
    __syncthreads();
    for (int s = 128; s; s >>= 1) {
        if (threadIdx.x < s) { r1[threadIdx.x] |= r1[threadIdx.x+s]; r3[threadIdx.x] |= r3[threadIdx.x+s]; }
        __syncthreads();
    }
    if (threadIdx.x == 0) g_mask_kind = r1[0] ? 1 : (r3[0] ? 2 : 0);
}
__global__ void mask_expand(const void* __restrict__ m) {
    int s = blockIdx.x * 256 + threadIdx.x;
    if (s >= BB*TT) return;
    int kind = g_mask_kind;
    float v;
    if (kind == 1)      v = ((const uint8_t*)m)[s] ? 1.0f : 0.0f;
    else if (kind == 2) v = (((const float*)m)[s] != 0.0f) ? 1.0f : 0.0f;
    else                v = ((const int*)m)[s] ? 1.0f : 0.0f;
    g_mask[s] = v;
}

// ---------------- prep: split x and W into bf16 hi/lo ----------------
__global__ __launch_bounds__(256) void prep_kernel(
    const float* __restrict__ x,  const float* __restrict__ Wq,
    const float* __restrict__ Wk, const float* __restrict__ Wv)
{
    const int y = blockIdx.y;
    const size_t i = (size_t)blockIdx.x * 256 + threadIdx.x;
    const float* src; __nv_bfloat16 *dh, *dl; size_t n4;
    if (y == 0) { src = x; dh = g_x_hi; dl = g_x_lo; n4 = (size_t)BB*TT*DD/4; }
    else {
        src = (y == 1) ? Wq : ((y == 2) ? Wk : Wv);
        dh = g_w_hi + (size_t)(y-1)*QD*DD; dl = g_w_lo + (size_t)(y-1)*QD*DD;
        n4 = (size_t)QD*DD/4;
    }
    if (i >= n4) return;
    float4 v = ((const float4*)src)[i];
    uint32_t h01, l01, h23, l23;
    split2(v.x, v.y, h01, l01);
    split2(v.z, v.w, h23, l23);
    ((uint2*)dh)[i] = make_uint2(h01, h23);
    ((uint2*)dl)[i] = make_uint2(l01, l23);
}

// ---------------- projection GEMM (bf16x3, cp.async, term-major MMA) ----------------
#define PJ_AH 0
#define PJ_AL 16384
#define PJ_BH 32768
#define PJ_BL 49152
#define PJ_STAGE 65536
#define PJ_SMEM (2*PJ_STAGE + 1024)

__global__ __launch_bounds__(256, 1) void proj_kernel()
{
    extern __shared__ char smraw[];
    char* sp = (char*)(((uintptr_t)smraw + 1023) & ~(uintptr_t)1023);
    uint32_t sb = smem_u32(sp);
    const int tid = threadIdx.x, lane = tid & 31, w = tid >> 5;
    const int m0 = blockIdx.x * 128, z = blockIdx.y;
    const int wm = w & 3, wn = w >> 2;
    const int mrow0 = wm * 32, ncol0 = wn * 64;

    const __nv_bfloat16* xh = g_x_hi;
    const __nv_bfloat16* xl = g_x_lo;
    const __nv_bfloat16* wh = g_w_hi + (size_t)z*QD*DD;
    const __nv_bfloat16* wl = g_w_lo + (size_t)z*QD*DD;

    const int mat = lane >> 3;
    const uint32_t xorv = (uint32_t)(lane & 7) << 4;
    const int rA = (mat & 1) * 8 + (lane & 7);
    const int cA = (mat >> 1) * 16;
    const int rB = (mat >> 1) * 8 + (lane & 7);
    const int cB = (mat & 1) * 16;

    const int srow = tid >> 3, sci = tid & 7;
    float C[2][8][4] = {};

    #define PJ_STAGE_CHUNK(c) do {                                              \
        const int _k0 = (c) * 64;                                               \
        uint32_t _bb = sb + (uint32_t)((c) & 1) * PJ_STAGE;                     \
        _Pragma("unroll")                                                       \
        for (int _r = 0; _r < 4; _r++) {                                        \
            int _row = srow + _r * 32;                                          \
            uint32_t _doff = (uint32_t)_row * 128 +                             \
                (((uint32_t)sci * 16) ^ ((uint32_t)(_row & 7) << 4));           \
            const size_t _go = (size_t)(m0 + _row) * DD + _k0 + sci * 8;        \
            const size_t _gw = (size_t)_row * DD + _k0 + sci * 8;               \
            cp16(_bb + PJ_AH + _doff, xh + _go);                                \
            cp16(_bb + PJ_AL + _doff, xl + _go);                                \
            cp16(_bb + PJ_BH + _doff, wh + _gw);                                \
            cp16(_bb + PJ_BL + _doff, wl + _gw);                                \
        } } while (0)

    PJ_STAGE_CHUNK(0); CP_COMMIT();

    for (int c = 0; c < 16; c++) {
        if (c + 1 < 16) { PJ_STAGE_CHUNK(c + 1); CP_COMMIT(); CP_WAIT(1); }
        else            { CP_WAIT(0); }
        __syncthreads();
        const uint32_t bb = sb + (uint32_t)(c & 1) * PJ_STAGE;

        #pragma unroll
        for (int ks = 0; ks < 4; ks++) {
            const int k0 = ks * 16;
            uint32_t ah[2][4], al[2][4];
            #pragma unroll
            for (int mt = 0; mt < 2; mt++) {
                uint32_t aoff = (uint32_t)(mrow0 + mt*16 + rA) * 128 + (((uint32_t)(k0*2 + cA)) ^ xorv);
                ldm4(ah[mt], bb + PJ_AH + aoff);
                ldm4(al[mt], bb + PJ_AL + aoff);
            }
            uint32_t bh[4][4], bl[4][4];
            #pragma unroll
            for (int nt2 = 0; nt2 < 4; nt2++) {
                const int n0 = ncol0 + nt2 * 16;
                uint32_t boff = (uint32_t)(n0 + rB) * 128 + (((uint32_t)(k0*2 + cB)) ^ xorv);
                ldm4(bh[nt2], bb + PJ_BH + boff);
                ldm4(bl[nt2], bb + PJ_BL + boff);
            }
            // term-major: all hi*hi, then hi*lo, then lo*hi (RAW distance 16)
            #pragma unroll
            for (int nt2 = 0; nt2 < 4; nt2++)
                #pragma unroll
                for (int mt = 0; mt < 2; mt++) {
                    mma_bf16(C[mt][nt2*2],   ah[mt], bh[nt2]);
                    mma_bf16(C[mt][nt2*2+1], ah[mt], bh[nt2] + 2);
                }
            #pragma unroll
            for (int nt2 = 0; nt2 < 4; nt2++)
                #pragma unroll
                for (int mt = 0; mt < 2; mt++) {
                    mma_bf16(C[mt][nt2*2],   ah[mt], bl[nt2]);
                    mma_bf16(C[mt][nt2*2+1], ah[mt], bl[nt2] + 2);
                }
            #pragma unroll
            for (int nt2 = 0; nt2 < 4; nt2++)
                #pragma unroll
                for (int mt = 0; mt < 2; mt++) {
                    mma_bf16(C[mt][nt2*2],   al[mt], bh[nt2]);
                    mma_bf16(C[mt][nt2*2+1], al[mt], bh[nt2] + 2);
                }
        }
        __syncthreads();
    }

    __nv_bfloat16 *dh, *dl;
    if (z == 0)      { dh = g_q_hi; dl = g_q_lo; }
    else if (z == 1) { dh = g_k_hi; dl = g_k_lo; }
    else             { dh = g_v_hi; dl = g_v_lo; }
    const int r = lane >> 2, c2 = 2 * (lane & 3);
    #pragma unroll
    for (int mt = 0; mt < 2; mt++) {
        #pragma unroll
        for (int nt = 0; nt < 8; nt++) {
            int cc = ncol0 + nt * 8 + c2;
            size_t mg0 = (size_t)(m0 + mrow0 + mt*16 + r);
            uint32_t h, l;
            split2(C[mt][nt][0], C[mt][nt][1], h, l);
            *(uint32_t*)(dh + mg0*QD + cc) = h;
            *(uint32_t*)(dl + mg0*QD + cc) = l;
            split2(C[mt][nt][2], C[mt][nt][3], h, l);
            *(uint32_t*)(dh + (mg0+8)*QD + cc) = h;
            *(uint32_t*)(dl + (mg0+8)*QD + cc) = l;
        }
    }
}

// ---------------- flash attention (bf16x3, phase-pipelined, term-major) ----------------
#define AT_QH 0
#define AT_QL 32768
#define AT_KH 65536
#define AT_KL 98304
#define AT_VH 131072
#define AT_VL 163840
#define AT_MK 196608
#define AT_SMEM (196608 + 512 + 1024)

__global__ __launch_bounds__(256, 1) void attn_kernel(float* __restrict__ out)
{
    extern __shared__ char smraw[];
    char* sp = (char*)(((uintptr_t)smraw + 1023) & ~(uintptr_t)1023);
    uint32_t sb = smem_u32(sp);
    float* mkS = (float*)(sp + AT_MK);
    const int tid = threadIdx.x, lane = tid & 31, w = tid >> 5;
    const int b = blockIdx.y, t0 = blockIdx.x * 128;
    const int m0w = w * 16;

    const int mat = lane >> 3;
    const uint32_t xorv = (uint32_t)(lane & 7) << 4;
    const int rA = (mat & 1) * 8 + (lane & 7);
    const int cA = (mat >> 1) * 16;
    const int rB = (mat >> 1) * 8 + (lane & 7);
    const int cB = (mat & 1) * 16;

    const int srow = tid >> 4, sci = tid & 15;

    #define AT_ISSUE_K(it) do {                                                 \
        const int _s0 = (it) * 128;                                             \
        _Pragma("unroll")                                                       \
        for (int _r = 0; _r < 8; _r++) {                                        \
            int _row = srow + _r * 16;                                          \
            uint32_t _doff = (uint32_t)_row * 256 +                             \
                (((uint32_t)sci * 16) ^ ((uint32_t)(_row & 7) << 4));           \
            const size_t _g = (size_t)(b*TT + _s0 + _row) * QD + sci * 8;       \
            cp16(sb + AT_KH + _doff, g_k_hi + _g);                              \
            cp16(sb + AT_KL + _doff, g_k_lo + _g);                              \
        }                                                                       \
        if (tid < 32) cp16(sb + AT_MK + tid*16, g_mask + b*TT + _s0 + tid*4);   \
    } while (0)

    #define AT_ISSUE_V(it) do {                                                 \
        const int _s0 = (it) * 128;                                             \
        _Pragma("unroll")                                                       \
        for (int _r = 0; _r < 8; _r++) {                                        \
            int _row = srow + _r * 16;                                          \
            uint32_t _doff = (uint32_t)_row * 256 +                             \
                (((uint32_t)sci * 16) ^ ((uint32_t)(_row & 7) << 4));           \
            const size_t _g = (size_t)(b*TT + _s0 + _row) * QD + sci * 8;       \
            cp16(sb + AT_VH + _doff, g_v_hi + _g);                              \
            cp16(sb + AT_VL + _doff, g_v_lo + _g);                              \
        } } while (0)

    AT_ISSUE_K(0); CP_COMMIT();
    AT_ISSUE_V(0); CP_COMMIT();

    {
        const uint4* qh = (const uint4*)(g_q_hi + (size_t)(b*TT + t0) * QD);
        const uint4* ql = (const uint4*)(g_q_lo + (size_t)(b*TT + t0) * QD);
        #pragma unroll
        for (int r = 0; r < 8; r++) {
            int idx = tid + r * 256;
            int row = idx >> 4;
            uint32_t cb = (uint32_t)(idx & 15) * 16;
            uint32_t doff = (uint32_t)row * 256 + (cb ^ ((uint32_t)(row & 7) << 4));
            *(uint4*)(sp + AT_QH + doff) = qh[idx];
            *(uint4*)(sp + AT_QL + doff) = ql[idx];
        }
    }

    float O[16][4] = {};
    float m0r = -1.0e30f, m1r = -1.0e30f, s0r = 0.0f, s1r = 0.0f;
    const int c2 = 2 * (lane & 3);

    for (int it = 0; it < 16; it++) {
        CP_WAIT(1);
        __syncthreads();

        // S = Q K^T  (term-major in groups of 2 output tiles)
        float S[16][4] = {};
        #pragma unroll
        for (int ks = 0; ks < 8; ks++) {
            const int k0 = ks * 16;
            uint32_t aqh[4], aql[4];
            uint32_t aoff = (uint32_t)(m0w + rA) * 256 + (((uint32_t)(k0*2 + cA)) ^ xorv);
            ldm4(aqh, sb + AT_QH + aoff);
            ldm4(aql, sb + AT_QL + aoff);
            #pragma unroll
            for (int g = 0; g < 4; g++) {
                uint32_t bh[2][4], bl[2][4];
                #pragma unroll
                for (int j = 0; j < 2; j++) {
                    const int n0 = (g*2 + j) * 16;
                    uint32_t boff = (uint32_t)(n0 + rB) * 256 + (((uint32_t)(k0*2 + cB)) ^ xorv);
                    ldm4(bh[j], sb + AT_KH + boff);
                    ldm4(bl[j], sb + AT_KL + boff);
                }
                #pragma unroll
                for (int j = 0; j < 2; j++) {
                    mma_bf16(S[(g*2+j)*2],   aqh, bh[j]);
                    mma_bf16(S[(g*2+j)*2+1], aqh, bh[j] + 2);
                }
                #pragma unroll
                for (int j = 0; j < 2; j++) {
                    mma_bf16(S[(g*2+j)*2],   aqh, bl[j]);
                    mma_bf16(S[(g*2+j)*2+1], aqh, bl[j] + 2);
                }
                #pragma unroll
                for (int j = 0; j < 2; j++) {
                    mma_bf16(S[(g*2+j)*2],   aql, bh[j]);
                    mma_bf16(S[(g*2+j)*2+1], aql, bh[j] + 2);
                }
            }
        }

        // masked online softmax
        float mx0 = -3.0e38f, mx1 = -3.0e38f;
        #pragma unroll
        for (int nt = 0; nt < 16; nt++) {
            float k0m = mkS[nt*8 + c2], k1m = mkS[nt*8 + c2 + 1];
            S[nt][0] = (k0m != 0.0f) ? S[nt][0] : -3.0e38f;
            S[nt][1] = (k1m != 0.0f) ? S[nt][1] : -3.0e38f;
            S[nt][2] = (k0m != 0.0f) ? S[nt][2] : -3.0e38f;
            S[nt][3] = (k1m != 0.0f) ? S[nt][3] : -3.0e38f;
            mx0 = fmaxf(mx0, fmaxf(S[nt][0], S[nt][1]));
            mx1 = fmaxf(mx1, fmaxf(S[nt][2], S[nt][3]));
        }
        mx0 = fmaxf(mx0, __shfl_xor_sync(0xffffffffu, mx0, 1));
        mx0 = fmaxf(mx0, __shfl_xor_sync(0xffffffffu, mx0, 2));
        mx1 = fmaxf(mx1, __shfl_xor_sync(0xffffffffu, mx1, 1));
        mx1 = fmaxf(mx1, __shfl_xor_sync(0xffffffffu, mx1, 2));
        float mn0 = fmaxf(m0r, mx0), mn1 = fmaxf(m1r, mx1);
        float sc0 = __expf(m0r - mn0), sc1 = __expf(m1r - mn1);
        float sum0 = 0.0f, sum1 = 0.0f;
        #pragma unroll
        for (int nt = 0; nt < 16; nt++) {
            S[nt][0] = __expf(S[nt][0] - mn0);
            S[nt][1] = __expf(S[nt][1] - mn0);
            S[nt][2] = __expf(S[nt][2] - mn1);
            S[nt][3] = __expf(S[nt][3] - mn1);
            sum0 += S[nt][0] + S[nt][1];
            sum1 += S[nt][2] + S[nt][3];
        }
        sum0 += __shfl_xor_sync(0xffffffffu, sum0, 1);
        sum0 += __shfl_xor_sync(0xffffffffu, sum0, 2);
        sum1 += __shfl_xor_sync(0xffffffffu, sum1, 1);
        sum1 += __shfl_xor_sync(0xffffffffu, sum1, 2);
        s0r = s0r * sc0 + sum0;  s1r = s1r * sc1 + sum1;
        m0r = mn0;  m1r = mn1;

        __syncthreads();
        if (it + 1 < 16) { AT_ISSUE_K(it + 1); CP_COMMIT(); CP_WAIT(1); }
        else             { CP_WAIT(0); }
        __syncthreads();

        #pragma unroll
        for (int nt = 0; nt < 16; nt++) {
            O[nt][0] *= sc0; O[nt][1] *= sc0;
            O[nt][2] *= sc1; O[nt][3] *= sc1;
        }

        // O += P V  (term-major in groups of 2)
        #pragma unroll
        for (int ks = 0; ks < 8; ks++) {
            uint32_t ah[4], al[4];
            split2(S[2*ks][0],   S[2*ks][1],   ah[0], al[0]);
            split2(S[2*ks][2],   S[2*ks][3],   ah[1], al[1]);
            split2(S[2*ks+1][0], S[2*ks+1][1], ah[2], al[2]);
            split2(S[2*ks+1][2], S[2*ks+1][3], ah[3], al[3]);
            const int sv0 = ks * 16;
            #pragma unroll
            for (int g = 0; g < 4; g++) {
                uint32_t bvh[2][4], bvl[2][4];
                #pragma unroll
                for (int j = 0; j < 2; j++) {
                    const int d0 = (g*2 + j) * 16;
                    uint32_t voff = (uint32_t)(sv0 + rA) * 256 + (((uint32_t)(d0*2 + cA)) ^ xorv);
                    ldm4t(bvh[j], sb + AT_VH + voff);
                    ldm4t(bvl[j], sb + AT_VL + voff);
                }
                #pragma unroll
                for (int j = 0; j < 2; j++) {
                    mma_bf16(O[(g*2+j)*2],   ah, bvh[j]);
                    mma_bf16(O[(g*2+j)*2+1], ah, bvh[j] + 2);
                }
                #pragma unroll
                for (int j = 0; j < 2; j++) {
                    mma_bf16(O[(g*2+j)*2],   ah, bvl[j]);
                    mma_bf16(O[(g*2+j)*2+1], ah, bvl[j] + 2);
                }
                #pragma unroll
                for (int j = 0; j < 2; j++) {
                    mma_bf16(O[(g*2+j)*2],   al, bvh[j]);
                    mma_bf16(O[(g*2+j)*2+1], al, bvh[j] + 2);
                }
            }
        }
        __syncthreads();
        if (it + 1 < 16) { AT_ISSUE_V(it + 1); CP_COMMIT(); }
    }

    const float inv0 = (s0r > 0.0f) ? 1.0f / s0r : 0.0f;
    const float inv1 = (s1r > 0.0f) ? 1.0f / s1r : 0.0f;
    const size_t row0 = (size_t)b*TT + t0 + m0w + (lane >> 2);
    #pragma unroll
    for (int nt = 0; nt < 16; nt++) {
        int col = nt * 8 + c2;
        *(float2*)(out + row0*QD + col)     = make_float2(O[nt][0]*inv0, O[nt][1]*inv0);
        *(float2*)(out + (row0+8)*QD + col) = make_float2(O[nt][2]*inv1, O[nt][3]*inv1);
    }
}

// ---------------- launch ----------------
extern "C" void kernel_launch(void* const* d_in, const int* in_sizes, int n_in,
                              void* d_out, int out_size)
{
    const float* x  = (const float*)d_in[0];
    const void*  mk = d_in[1];
    const float* Wq = (const float*)d_in[2];
    const float* Wk = (const float*)d_in[3];
    const float* Wv = (const float*)d_in[4];
    float* out = (float*)d_out;
    (void)in_sizes; (void)n_in; (void)out_size;

    mask_sniff<<<1, 256>>>((const uint8_t*)mk);
    mask_expand<<<(BB*TT + 255)/256, 256>>>(mk);

    dim3 gp((BB*TT*DD/4 + 255)/256, 4);
    prep_kernel<<<gp, 256>>>(x, Wq, Wk, Wv);

    cudaFuncSetAttribute(proj_kernel, cudaFuncAttributeMaxDynamicSharedMemorySize, PJ_SMEM);
    cudaFuncSetAttribute(attn_kernel, cudaFuncAttributeMaxDynamicSharedMemorySize, AT_SMEM);

    dim3 g1(128, 3);
    proj_kernel<<<g1, 256, PJ_SMEM>>>();
    dim3 g2(16, 8);
    attn_kernel<<<g2, 256, AT_SMEM>>>(out);
}